// round 3
// baseline (speedup 1.0000x reference)
#include <cuda_runtime.h>
#include <math.h>
#include <stdint.h>

#define NPTS   131072
#define PB     16384
#define BATCH  8
#define MTOK   128
#define KNN    16
#define TOKD   768
#define PFSTRIDE 776   // 768 pf + 4 coords + 4 zero pad (K multiple of 8)

// ---------------- scratch (device globals; no allocs allowed) ----------------
__device__ float g_x8[NPTS*8];
__device__ float g_w1p[8*256];
__device__ float g_iw1p[PFSTRIDE*256];
__device__ float g_c4[NPTS*4];
__device__ float g_h1[NPTS*256];
__device__ float g_h2[(size_t)NPTS*512];
__device__ float g_h3[(size_t)NPTS*768];
__device__ float g_pfc[(size_t)NPTS*PFSTRIDE];
__device__ float g_z1[NPTS*256];
__device__ float g_z2[NPTS*256];
__device__ float g_z3[NPTS*256];
__device__ float g_imp[NPTS];
__device__ int   g_sel[BATCH*MTOK];
__device__ float g_cent[BATCH*MTOK*4];
__device__ int   g_order[BATCH*MTOK];
__device__ int   g_knn[BATCH*MTOK*KNN];
__device__ float g_pooled[BATCH*MTOK*TOKD];
__device__ float g_t1[BATCH*MTOK*TOKD];
__device__ float g_tok[BATCH*MTOK*TOKD];

// ---------------- prep: pad features to K=8, extract coords, pad pfc --------
__global__ void prep_points(const float* __restrict__ coords,
                            const float* __restrict__ feats)
{
    int i = blockIdx.x*blockDim.x + threadIdx.x;
    if (i >= NPTS) return;
    #pragma unroll
    for (int j=0;j<6;j++) g_x8[i*8+j] = feats[i*6+j];
    g_x8[i*8+6]=0.f; g_x8[i*8+7]=0.f;
    #pragma unroll
    for (int j=0;j<4;j++){
        float c = coords[i*5+1+j];
        g_c4[i*4+j] = c;
        g_pfc[(size_t)i*PFSTRIDE+768+j] = c;
        g_pfc[(size_t)i*PFSTRIDE+772+j] = 0.f;
    }
}

__global__ void prep_w(const float* __restrict__ w1, const float* __restrict__ iw1)
{
    int idx = blockIdx.x*blockDim.x + threadIdx.x;
    if (idx < 8*256)            g_w1p[idx]  = (idx < 6*256)   ? w1[idx]  : 0.f;
    if (idx < PFSTRIDE*256)     g_iw1p[idx] = (idx < 772*256) ? iw1[idx] : 0.f;
}

// ---------------- SGEMM: C[M,N] = act(A[M,K] @ B[K,N] + bias) ---------------
// 128x128 block tile, BK=8, 256 threads, 8x8 per-thread, double-buffered smem.
// Requires M%128==0, N%128==0, K%8==0, 16B-aligned pointers/strides.
template<bool RELU>
__global__ __launch_bounds__(256,2) void sgemm128(
    const float* __restrict__ A, int lda,
    const float* __restrict__ B, int N,
    const float* __restrict__ bias,
    float* __restrict__ C, int ldc, int K)
{
    __shared__ float As[2][8][128];
    __shared__ float Bs[2][8][128];
    const int tid  = threadIdx.x;
    const int bm   = blockIdx.y * 128;
    const int bn   = blockIdx.x * 128;
    const int arow = tid >> 1;
    const int acol = (tid & 1) * 4;
    const int brow = tid >> 5;
    const int bcol = (tid & 31) * 4;
    const int tx   = tid & 15;
    const int ty   = tid >> 4;

    const float* Aptr = A + (size_t)(bm + arow) * lda + acol;
    const float* Bptr = B + (size_t)brow * N + bn + bcol;

    float acc[8][8];
    #pragma unroll
    for (int i=0;i<8;i++)
        #pragma unroll
        for (int j=0;j<8;j++) acc[i][j]=0.f;

    {
        float4 a = *(const float4*)Aptr;
        As[0][acol+0][arow]=a.x; As[0][acol+1][arow]=a.y;
        As[0][acol+2][arow]=a.z; As[0][acol+3][arow]=a.w;
        *(float4*)&Bs[0][brow][bcol] = *(const float4*)Bptr;
    }
    __syncthreads();

    const int ktiles = K >> 3;
    int buf = 0;
    for (int kt=0; kt<ktiles; kt++){
        float4 a, bv;
        const bool has = (kt+1 < ktiles);
        if (has){
            a  = *(const float4*)(Aptr + (kt+1)*8);
            bv = *(const float4*)(Bptr + (size_t)(kt+1)*8*N);
        }
        #pragma unroll
        for (int k=0;k<8;k++){
            float4 a0 = *(const float4*)&As[buf][k][ty*4];
            float4 a1 = *(const float4*)&As[buf][k][64+ty*4];
            float4 b0 = *(const float4*)&Bs[buf][k][tx*4];
            float4 b1 = *(const float4*)&Bs[buf][k][64+tx*4];
            float ar[8] = {a0.x,a0.y,a0.z,a0.w,a1.x,a1.y,a1.z,a1.w};
            float br[8] = {b0.x,b0.y,b0.z,b0.w,b1.x,b1.y,b1.z,b1.w};
            #pragma unroll
            for (int i=0;i<8;i++)
                #pragma unroll
                for (int j=0;j<8;j++)
                    acc[i][j] += ar[i]*br[j];
        }
        if (has){
            const int nb = buf^1;
            As[nb][acol+0][arow]=a.x; As[nb][acol+1][arow]=a.y;
            As[nb][acol+2][arow]=a.z; As[nb][acol+3][arow]=a.w;
            *(float4*)&Bs[nb][brow][bcol] = bv;
        }
        __syncthreads();
        buf ^= 1;
    }

    float4 bv0 = *(const float4*)(bias + bn + tx*4);
    float4 bv1 = *(const float4*)(bias + bn + 64 + tx*4);
    #pragma unroll
    for (int i=0;i<8;i++){
        const int row = bm + ((i<4) ? (ty*4+i) : (64 + ty*4 + i - 4));
        float4 o0, o1;
        o0.x=acc[i][0]+bv0.x; o0.y=acc[i][1]+bv0.y; o0.z=acc[i][2]+bv0.z; o0.w=acc[i][3]+bv0.w;
        o1.x=acc[i][4]+bv1.x; o1.y=acc[i][5]+bv1.y; o1.z=acc[i][6]+bv1.z; o1.w=acc[i][7]+bv1.w;
        if (RELU){
            o0.x=fmaxf(o0.x,0.f); o0.y=fmaxf(o0.y,0.f); o0.z=fmaxf(o0.z,0.f); o0.w=fmaxf(o0.w,0.f);
            o1.x=fmaxf(o1.x,0.f); o1.y=fmaxf(o1.y,0.f); o1.z=fmaxf(o1.z,0.f); o1.w=fmaxf(o1.w,0.f);
        }
        *(float4*)(C + (size_t)row*ldc + bn + tx*4)      = o0;
        *(float4*)(C + (size_t)row*ldc + bn + 64 + tx*4) = o1;
    }
}

// ---------------- LayerNorm over rows of 256 (warp per row) -----------------
__global__ void ln_kernel(const float* __restrict__ z, const float* __restrict__ gg,
                          const float* __restrict__ bb, float* __restrict__ o)
{
    int row  = blockIdx.x*8 + (threadIdx.x>>5);
    int lane = threadIdx.x & 31;
    const float* r = z + (size_t)row*256 + lane*8;
    float v[8];
    float4 p0 = *(const float4*)r;
    float4 p1 = *(const float4*)(r+4);
    v[0]=p0.x;v[1]=p0.y;v[2]=p0.z;v[3]=p0.w;v[4]=p1.x;v[5]=p1.y;v[6]=p1.z;v[7]=p1.w;
    float s=0.f;
    #pragma unroll
    for (int j=0;j<8;j++) s+=v[j];
    #pragma unroll
    for (int off=16;off>0;off>>=1) s += __shfl_xor_sync(0xffffffffu, s, off);
    float mu = s * (1.f/256.f);
    float q=0.f;
    #pragma unroll
    for (int j=0;j<8;j++){ float d=v[j]-mu; q+=d*d; }
    #pragma unroll
    for (int off=16;off>0;off>>=1) q += __shfl_xor_sync(0xffffffffu, q, off);
    float inv = rsqrtf(q*(1.f/256.f) + 1e-5f);
    float* out = o + (size_t)row*256 + lane*8;
    #pragma unroll
    for (int j=0;j<8;j++)
        out[j] = (v[j]-mu)*inv*gg[lane*8+j] + bb[lane*8+j];
}

// ---------------- importance scalar: dot(z_row, iw3) + ib3 ------------------
__global__ void imp_kernel(const float* __restrict__ z, const float* __restrict__ iw3,
                           const float* __restrict__ ib3, float* __restrict__ imp)
{
    int row  = blockIdx.x*8 + (threadIdx.x>>5);
    int lane = threadIdx.x & 31;
    const float* r = z + (size_t)row*256 + lane*8;
    float s = 0.f;
    #pragma unroll
    for (int j=0;j<8;j++) s += r[j]*iw3[lane*8+j];
    #pragma unroll
    for (int off=16;off>0;off>>=1) s += __shfl_xor_sync(0xffffffffu, s, off);
    if (lane==0) imp[row] = s + ib3[0];
}

// monotone float->uint map (ascending)
__device__ __forceinline__ unsigned f2u(float x){
    unsigned u = __float_as_uint(x);
    return (u & 0x80000000u) ? ~u : (u | 0x80000000u);
}

// ---------------- per-batch top-128 via exact MSB radix select --------------
__global__ void topk_kernel(const float* __restrict__ imp, const float* __restrict__ noise,
                            const float* __restrict__ logt, const float* __restrict__ c4,
                            int* __restrict__ sel, float* __restrict__ cent)
{
    extern __shared__ unsigned skey[];          // 16384 keys
    __shared__ unsigned hist[256];
    __shared__ unsigned s_prefix, s_mask;
    __shared__ int s_rem, s_cnt, s_eqcnt;
    __shared__ int eqbuf[512];
    const int b = blockIdx.x;
    const int tid = threadIdx.x;                // 1024 threads
    const float temp = fmaxf(expf(logt[0]), 0.1f);
    for (int i=tid;i<PB;i+=1024){
        float v = (imp[b*PB+i] + noise[b*PB+i]) / temp;
        skey[i] = f2u(v);
    }
    if (tid==0){ s_prefix=0u; s_mask=0u; s_rem=MTOK; }
    __syncthreads();
    for (int round=0; round<4; round++){
        const int shift = 24 - 8*round;
        if (tid<256) hist[tid]=0u;
        __syncthreads();
        unsigned mask = s_mask, prefix = s_prefix;
        for (int i=tid;i<PB;i+=1024){
            unsigned k = skey[i];
            if ((k & mask) == prefix) atomicAdd(&hist[(k>>shift)&255u], 1u);
        }
        __syncthreads();
        if (tid==0){
            int rem = s_rem; unsigned cum=0; int bsel=0;
            for (int bin=255; bin>=0; bin--){
                if (cum + hist[bin] >= (unsigned)rem){ bsel=bin; break; }
                cum += hist[bin];
            }
            s_rem    = rem - (int)cum;
            s_prefix = prefix | ((unsigned)bsel << shift);
            s_mask   = mask   | (0xFFu << shift);
        }
        __syncthreads();
    }
    const unsigned kth = s_prefix;
    const int rEq = s_rem;
    if (tid==0){ s_cnt=0; s_eqcnt=0; }
    __syncthreads();
    for (int i=tid;i<PB;i+=1024){
        unsigned k = skey[i];
        if (k > kth){
            int p = atomicAdd(&s_cnt,1);
            sel[b*MTOK+p] = i;
        } else if (k == kth){
            int p = atomicAdd(&s_eqcnt,1);
            if (p < 512) eqbuf[p] = i;
        }
    }
    __syncthreads();
    if (tid==0){
        int e = min(s_eqcnt, 512);
        for (int a=1;a<e;a++){           // insertion sort: ties -> lowest index first
            int v=eqbuf[a]; int c=a-1;
            while (c>=0 && eqbuf[c]>v){ eqbuf[c+1]=eqbuf[c]; c--; }
            eqbuf[c+1]=v;
        }
        int base = s_cnt;
        for (int a=0;a<rEq;a++) sel[b*MTOK+base+a] = eqbuf[a];
    }
    __syncthreads();
    for (int j=tid;j<MTOK;j+=1024){
        int s = sel[b*MTOK+j];
        int g = b*PB + s;
        #pragma unroll
        for (int q=0;q<4;q++) cent[(b*MTOK+j)*4+q] = c4[g*4+q];
    }
}

// ---------------- stable sort of 128 cents by t (bitonic on (t,slot)) -------
__global__ void sortt_kernel(const float* __restrict__ cent, int* __restrict__ order)
{
    __shared__ unsigned long long s[128];
    const int b = blockIdx.x, tid = threadIdx.x;
    float t = cent[(b*MTOK+tid)*4+3];
    s[tid] = ((unsigned long long)f2u(t) << 32) | (unsigned)tid;
    __syncthreads();
    for (int ksz=2; ksz<=128; ksz<<=1){
        for (int j=ksz>>1; j>0; j>>=1){
            int ixj = tid ^ j;
            if (ixj > tid){
                unsigned long long a = s[tid], c = s[ixj];
                bool up = ((tid & ksz) == 0);
                if (up ? (a > c) : (a < c)){ s[tid]=c; s[ixj]=a; }
            }
            __syncthreads();
        }
    }
    order[b*MTOK+tid] = (int)(s[tid] & 0xffffffffu);
}

// ---------------- brute-force 16-NN per cent (lexi (d2,idx) keys) -----------
__global__ void knn_kernel(const float* __restrict__ c4, const float* __restrict__ cent,
                           int* __restrict__ knn)
{
    __shared__ unsigned long long lists[128][KNN];
    const int bm = blockIdx.x;          // 0..1023
    const int b  = bm >> 7;
    const int tid = threadIdx.x;        // 128
    const float cx = cent[bm*4+0], cy = cent[bm*4+1], cz = cent[bm*4+2], ct = cent[bm*4+3];
    unsigned long long loc[KNN];
    #pragma unroll
    for (int q=0;q<KNN;q++) loc[q] = ~0ull;
    const float* cb = c4 + (size_t)b*PB*4;
    for (int i=tid;i<PB;i+=128){
        float4 p = *(const float4*)(cb + (size_t)i*4);
        float dx=p.x-cx, dy=p.y-cy, dz=p.z-cz, dt=p.w-ct;
        float d2 = dx*dx + dy*dy + dz*dz + dt*dt;
        unsigned long long key = ((unsigned long long)(__float_as_uint(d2)|0x80000000u) << 32) | (unsigned)i;
        if (key < loc[KNN-1]){
            loc[KNN-1] = key;
            #pragma unroll
            for (int q=KNN-1;q>0;q--){
                if (loc[q] < loc[q-1]){ unsigned long long t=loc[q]; loc[q]=loc[q-1]; loc[q-1]=t; }
            }
        }
    }
    #pragma unroll
    for (int q=0;q<KNN;q++) lists[tid][q]=loc[q];
    __syncthreads();
    for (int sgap=64; sgap>0; sgap>>=1){
        if (tid < sgap){
            unsigned long long out[KNN];
            int i1=0, i2=0;
            #pragma unroll
            for (int q=0;q<KNN;q++){
                unsigned long long a=lists[tid][i1], c=lists[tid+sgap][i2];
                if (a<=c){ out[q]=a; i1++; } else { out[q]=c; i2++; }
            }
            #pragma unroll
            for (int q=0;q<KNN;q++) lists[tid][q]=out[q];
        }
        __syncthreads();
    }
    if (tid < KNN) knn[bm*KNN+tid] = (int)(lists[0][tid] & 0xffffffffu);
}

// ---------------- gather neighbor pf rows + max pool ------------------------
__global__ void pool_kernel(const int* __restrict__ knn, float* __restrict__ pooled)
{
    __shared__ int nb[KNN];
    const int bm = blockIdx.x;
    const int b  = bm >> 7;
    const int tid = threadIdx.x;   // 256
    if (tid < KNN) nb[tid] = b*PB + knn[bm*KNN+tid];
    __syncthreads();
    for (int c=tid;c<TOKD;c+=256){
        float m = -3.402823466e38f;
        #pragma unroll
        for (int j=0;j<KNN;j++){
            float v = g_pfc[(size_t)nb[j]*PFSTRIDE + c];
            m = fmaxf(m, v);
        }
        pooled[(size_t)bm*TOKD + c] = m;
    }
}

// ---------------- scatter to output in time order ---------------------------
__global__ void out_kernel(const float* __restrict__ tok, const float* __restrict__ cent,
                           const int* __restrict__ order, float* __restrict__ out)
{
    const int bj = blockIdx.x;          // 0..1023
    const int b  = bj >> 7;
    const int o  = order[bj];
    const float* src = tok + (size_t)(b*MTOK+o)*TOKD;
    float* dst = out + (size_t)bj*TOKD;
    for (int c=threadIdx.x;c<TOKD;c+=256) dst[c]=src[c];
    if (threadIdx.x < 4) out[(size_t)BATCH*MTOK*TOKD + bj*4 + threadIdx.x] = cent[(b*MTOK+o)*4+threadIdx.x];
    if (threadIdx.x == 4) out[(size_t)BATCH*MTOK*TOKD + (size_t)BATCH*MTOK*4 + bj] = 1.0f;
}

// ---------------- launch ----------------------------------------------------
extern "C" void kernel_launch(void* const* d_in, const int* in_sizes, int n_in,
                              void* d_out, int out_size)
{
    (void)in_sizes; (void)n_in; (void)out_size;
    const float* coords = (const float*)d_in[0];
    const float* feats  = (const float*)d_in[1];
    const float* logt   = (const float*)d_in[2];
    const float* w1  = (const float*)d_in[3];  const float* b1  = (const float*)d_in[4];
    const float* w2  = (const float*)d_in[5];  const float* b2  = (const float*)d_in[6];
    const float* w3  = (const float*)d_in[7];  const float* b3  = (const float*)d_in[8];
    const float* w4  = (const float*)d_in[9];  const float* b4  = (const float*)d_in[10];
    const float* iw1 = (const float*)d_in[11]; const float* ib1 = (const float*)d_in[12];
    const float* lng = (const float*)d_in[13]; const float* lnb = (const float*)d_in[14];
    const float* iw2 = (const float*)d_in[15]; const float* ib2 = (const float*)d_in[16];
    const float* iw3 = (const float*)d_in[17]; const float* ib3 = (const float*)d_in[18];
    const float* nw1 = (const float*)d_in[19]; const float* nb1 = (const float*)d_in[20];
    const float* nw2 = (const float*)d_in[21]; const float* nb2 = (const float*)d_in[22];
    const float* noise = (const float*)d_in[23];

    void *px8,*pw1p,*piw1p,*pc4,*ph1,*ph2,*ph3,*ppfc,*pz1,*pz2,*pz3,*pimp;
    void *psel,*pcent,*pord,*pknn,*ppool,*pt1,*ptok;
    cudaGetSymbolAddress(&px8,  g_x8);   cudaGetSymbolAddress(&pw1p, g_w1p);
    cudaGetSymbolAddress(&piw1p,g_iw1p); cudaGetSymbolAddress(&pc4,  g_c4);
    cudaGetSymbolAddress(&ph1,  g_h1);   cudaGetSymbolAddress(&ph2,  g_h2);
    cudaGetSymbolAddress(&ph3,  g_h3);   cudaGetSymbolAddress(&ppfc, g_pfc);
    cudaGetSymbolAddress(&pz1,  g_z1);   cudaGetSymbolAddress(&pz2,  g_z2);
    cudaGetSymbolAddress(&pz3,  g_z3);   cudaGetSymbolAddress(&pimp, g_imp);
    cudaGetSymbolAddress(&psel, g_sel);  cudaGetSymbolAddress(&pcent,g_cent);
    cudaGetSymbolAddress(&pord, g_order);cudaGetSymbolAddress(&pknn, g_knn);
    cudaGetSymbolAddress(&ppool,g_pooled);
    cudaGetSymbolAddress(&pt1,  g_t1);   cudaGetSymbolAddress(&ptok, g_tok);

    prep_points<<<NPTS/256, 256>>>(coords, feats);
    prep_w<<<(PFSTRIDE*256+255)/256, 256>>>(w1, iw1);

    // MLP: 6(pad8)->256->512->768->768(pf)
    sgemm128<true ><<<dim3(2,1024),256>>>((const float*)px8, 8,   (const float*)pw1p, 256, b1, (float*)ph1, 256, 8);
    sgemm128<true ><<<dim3(4,1024),256>>>((const float*)ph1, 256, w2, 512, b2, (float*)ph2, 512, 256);
    sgemm128<true ><<<dim3(6,1024),256>>>((const float*)ph2, 512, w3, 768, b3, (float*)ph3, 768, 512);
    sgemm128<false><<<dim3(6,1024),256>>>((const float*)ph3, 768, w4, 768, b4, (float*)ppfc, PFSTRIDE, 768);

    // importance: concat(pf,c4) -> 256 -> LN -> 256 -> 1
    sgemm128<true ><<<dim3(2,1024),256>>>((const float*)ppfc, PFSTRIDE, (const float*)piw1p, 256, ib1, (float*)pz1, 256, PFSTRIDE);
    ln_kernel<<<NPTS/8, 256>>>((const float*)pz1, lng, lnb, (float*)pz2);
    sgemm128<true ><<<dim3(2,1024),256>>>((const float*)pz2, 256, iw2, 256, ib2, (float*)pz3, 256, 256);
    imp_kernel<<<NPTS/8, 256>>>((const float*)pz3, iw3, ib3, (float*)pimp);

    // selection + neighborhoods
    cudaFuncSetAttribute(topk_kernel, cudaFuncAttributeMaxDynamicSharedMemorySize, PB*4);
    topk_kernel<<<BATCH, 1024, PB*4>>>((const float*)pimp, noise, logt, (const float*)pc4,
                                       (int*)psel, (float*)pcent);
    sortt_kernel<<<BATCH, 128>>>((const float*)pcent, (int*)pord);
    knn_kernel<<<BATCH*MTOK, 128>>>((const float*)pc4, (const float*)pcent, (int*)pknn);
    pool_kernel<<<BATCH*MTOK, 256>>>((const int*)pknn, (float*)ppool);

    // token MLP: 768 -> 768 -> 768 (M = 1024)
    sgemm128<true ><<<dim3(6,8),256>>>((const float*)ppool, 768, nw1, 768, nb1, (float*)pt1, 768, 768);
    sgemm128<false><<<dim3(6,8),256>>>((const float*)pt1,   768, nw2, 768, nb2, (float*)ptok, 768, 768);

    out_kernel<<<BATCH*MTOK, 256>>>((const float*)ptok, (const float*)pcent, (const int*)pord, (float*)d_out);
}